// round 9
// baseline (speedup 1.0000x reference)
#include <cuda_runtime.h>
#include <cstdint>

// FGRU: B=64, T=1024, D=512, U=512, C=1024
// Persistent kernel: 128 CTAs x 512 threads, flag-array grid barriers.
// Direct-LDG GEMMs (no SMEM staging of activations), packed f32x2 FMA over
// K-parity, weight-stationary SMEM (pair-interleaved), x pre-transposed once.
//
// Global scratch (pair-interleaved over K so f32x2 needs no pack/unpack):
//   g_xT[t][kp][row*2+par]  : x transposed   (t<1024, kp<256, row<64, par<2)
//   g_hT[kp][row*2+par]     : hidden state   (u = 2*kp+par)
//   g_aT[kp][row*2+par]     : combined*gate  (k = 2*kp+par, k<1024)
//   g_zT[kp][row*2+par]     : pre-LN candidate

#define NCTA 128
#define NTHR 512

__device__ __align__(16) float g_xT[1024u * 512u * 64u];   // 128 MB
__device__ __align__(16) float g_hT[512 * 64];
__device__ __align__(16) float g_aT[1024 * 64];
__device__ __align__(16) float g_zT[512 * 64];
__device__ unsigned g_flag[NCTA];                          // zero-init

// SMEM layout (floats)
#define OFF_WG2 0                      // [512 kp][8 col][2 par] = 8192
#define OFF_WF2 8192                   // [512 kp][4 col][2 par] = 4096
#define OFF_RED 12288                  // [64 x 65] tile / reduction = 4160
#define SMEM_FLOATS 16448              // 65,792 bytes

#define FMA2(acc, a, b) \
    asm("fma.rn.f32x2 %0, %1, %2, %0;" : "+l"(acc) : "l"(a), "l"(b))

__device__ __forceinline__ float psum(unsigned long long v)
{
    return __uint_as_float((unsigned)v) + __uint_as_float((unsigned)(v >> 32));
}

__device__ __forceinline__ void gbar(unsigned target, int tid, int cta)
{
    __syncthreads();
    if (tid == 0) {
        __threadfence();
        *((volatile unsigned*)&g_flag[cta]) = target;
    }
    if (tid < NCTA) {
        while (*((volatile unsigned*)&g_flag[tid]) < target) { }
    }
    __threadfence();   // acquire: order subsequent data reads after flag obs
    __syncthreads();
}

__global__ void __launch_bounds__(NTHR, 1)
fgru_kernel(const float* __restrict__ x,      // [64][1024][512]
            const float* __restrict__ h0,     // [64][512]
            const float* __restrict__ Wg,     // [1024][1024]
            const float* __restrict__ bg,     // [1024]
            const float* __restrict__ Wf,     // [1024][512]
            const float* __restrict__ bf,     // [512]
            const float* __restrict__ gmm,    // [512]
            const float* __restrict__ bta,    // [512]
            float* __restrict__ y)            // [64][1024][512]
{
    extern __shared__ __align__(16) float sm[];
    float* red = sm + OFF_RED;

    const int tid  = threadIdx.x;
    const int cta  = blockIdx.x;
    const int gc0  = cta * 8;          // Wg column base
    const int fc0  = cta * 4;          // Wf column base
    const int lane = tid & 31;
    const int warp = tid >> 5;         // 0..15
    const int rowg = warp & 1;         // row group (rows 0-31 / 32-63)
    const int ks   = warp >> 1;        // k-split 0..7
    const int row  = rowg * 32 + lane;

    // ---------- one-time: weights into SMEM, pair-interleaved over k ----------
    for (int e = tid; e < 8192; e += NTHR) {
        int c = e & 7, k = e >> 3;
        sm[OFF_WG2 + (k >> 1) * 16 + c * 2 + (k & 1)] = Wg[k * 1024 + gc0 + c];
    }
    for (int e = tid; e < 4096; e += NTHR) {
        int c = e & 3, k = e >> 2;
        sm[OFF_WF2 + (k >> 1) * 8 + c * 2 + (k & 1)] = Wf[k * 512 + fc0 + c];
    }

    // ---------- one-time: h0 -> g_hT (pair-interleaved) ----------
    {
        int g = cta * NTHR + tid;
        if (g < 32768) {
            int u = g >> 6, r = g & 63;
            __stcg(&g_hT[(u >> 1) * 128 + r * 2 + (u & 1)], h0[r * 512 + u]);
        }
    }

    // ---------- one-time: transpose x -> g_xT (8 t-slices per CTA) ----------
    {
        float* tile = red;             // 64 x 65
        for (int i = 0; i < 8; ++i) {
            int t = cta * 8 + i;
            for (int kc = 0; kc < 8; ++kc) {
                __syncthreads();
                int kloc = tid & 63, rbase = tid >> 6;
                #pragma unroll
                for (int p = 0; p < 8; ++p) {
                    int r = p * 8 + rbase;
                    tile[kloc * 65 + r] =
                        x[((size_t)r * 1024 + t) * 512 + kc * 64 + kloc];
                }
                __syncthreads();
                #pragma unroll
                for (int it = 0; it < 2; ++it) {
                    int f4 = tid + NTHR * it;        // 0..1023
                    int kploc = f4 >> 5, q = f4 & 31;
                    float4 v;
                    v.x = tile[(2 * kploc) * 65 + 2 * q];
                    v.y = tile[(2 * kploc + 1) * 65 + 2 * q];
                    v.z = tile[(2 * kploc) * 65 + 2 * q + 1];
                    v.w = tile[(2 * kploc + 1) * 65 + 2 * q + 1];
                    reinterpret_cast<float4*>(g_xT)
                        [(size_t)t * 8192 + (kc * 32 + kploc) * 32 + q] = v;
                }
            }
        }
    }

    // ---------- barrier generation base (consistent across graph replays) ----
    __shared__ unsigned s_base;
    if (tid == 0) s_base = *((volatile unsigned*)&g_flag[cta]);
    __syncthreads();
    unsigned tgt = s_base;

    gbar(++tgt, tid, cta);   // init complete everywhere

    const ulonglong2* wg2 =
        reinterpret_cast<const ulonglong2*>(sm + OFF_WG2) + (ks * 64) * 4;
    const ulonglong2* wf2 =
        reinterpret_cast<const ulonglong2*>(sm + OFF_WF2) + (ks * 64) * 2;
    const unsigned long long* hT64 =
        reinterpret_cast<const unsigned long long*>(g_hT);
    const unsigned long long* aT64 =
        reinterpret_cast<const unsigned long long*>(g_aT);
    const unsigned long long* xT64 =
        reinterpret_cast<const unsigned long long*>(g_xT);

    for (int step = 0; step < 1024; ++step) {
        // ============ GEMM1: gate_pre = [x_t, h] @ Wg[:, gc0..gc0+8) =========
        {
            const unsigned long long* ap =
                (ks < 4) ? (xT64 + (size_t)step * 16384 + ks * 4096 + row)
                         : (hT64 + (ks - 4) * 4096 + row);
            const ulonglong2* wp = wg2;
            unsigned long long a0 = 0, a1 = 0, a2 = 0, a3 = 0,
                               a4 = 0, a5 = 0, a6 = 0, a7 = 0;
            #pragma unroll 4
            for (int kp = 0; kp < 64; ++kp) {
                unsigned long long av = __ldcg(ap); ap += 64;
                ulonglong2 w01 = wp[0], w23 = wp[1], w45 = wp[2], w67 = wp[3];
                wp += 4;
                FMA2(a0, av, w01.x); FMA2(a1, av, w01.y);
                FMA2(a2, av, w23.x); FMA2(a3, av, w23.y);
                FMA2(a4, av, w45.x); FMA2(a5, av, w45.y);
                FMA2(a6, av, w67.x); FMA2(a7, av, w67.y);
            }
            float* rb = red + row;
            rb[65 * (0 + 8 * ks)] = psum(a0);
            rb[65 * (1 + 8 * ks)] = psum(a1);
            rb[65 * (2 + 8 * ks)] = psum(a2);
            rb[65 * (3 + 8 * ks)] = psum(a3);
            rb[65 * (4 + 8 * ks)] = psum(a4);
            rb[65 * (5 + 8 * ks)] = psum(a5);
            rb[65 * (6 + 8 * ks)] = psum(a6);
            rb[65 * (7 + 8 * ks)] = psum(a7);
        }
        __syncthreads();

        // ============ epilogue 1: gate=sigmoid, a = combined*gate ============
        {
            int r = tid & 63, c = tid >> 6;       // c in 0..7
            float sum = 0.f;
            #pragma unroll
            for (int ss = 0; ss < 8; ++ss) sum += red[r + 65 * (c + 8 * ss)];
            int gc = gc0 + c;
            float pre  = sum + __ldg(&bg[gc]);
            float gate = 1.0f / (1.0f + __expf(-pre));
            float cv;
            if (gc0 < 512) {
                cv = __ldcg(&g_xT[(size_t)step * 32768 +
                                  (gc >> 1) * 128 + r * 2 + (gc & 1)]);
            } else {
                int u = gc - 512;
                cv = __ldcg(&g_hT[(u >> 1) * 128 + r * 2 + (u & 1)]);
            }
            __stcg(&g_aT[(gc >> 1) * 128 + r * 2 + (gc & 1)], cv * gate);
        }
        gbar(++tgt, tid, cta);   // barrier 1: a complete

        // ============ GEMM2: z_pre = a @ Wf[:, fc0..fc0+4) ===================
        {
            const unsigned long long* ap = aT64 + ks * 4096 + row;
            const ulonglong2* wp = wf2;
            unsigned long long z0 = 0, z1 = 0, z2 = 0, z3 = 0;
            #pragma unroll 4
            for (int kp = 0; kp < 64; ++kp) {
                unsigned long long av = __ldcg(ap); ap += 64;
                ulonglong2 w01 = wp[0], w23 = wp[1]; wp += 2;
                FMA2(z0, av, w01.x); FMA2(z1, av, w01.y);
                FMA2(z2, av, w23.x); FMA2(z3, av, w23.y);
            }
            float* rb = red + row;
            rb[65 * (0 + 4 * ks)] = psum(z0);
            rb[65 * (1 + 4 * ks)] = psum(z1);
            rb[65 * (2 + 4 * ks)] = psum(z2);
            rb[65 * (3 + 4 * ks)] = psum(z3);
        }
        __syncthreads();

        // ============ epilogue 2: silu -> g_zT ===============================
        if (tid < 256) {
            int r = tid & 63, c = tid >> 6;       // c in 0..3
            float sum = 0.f;
            #pragma unroll
            for (int ss = 0; ss < 8; ++ss) sum += red[r + 65 * (c + 4 * ss)];
            float z  = sum + __ldg(&bf[fc0 + c]);
            float zs = z / (1.0f + __expf(-z));   // silu
            int gz = fc0 + c;
            __stcg(&g_zT[(gz >> 1) * 128 + r * 2 + (gz & 1)], zs);
        }
        gbar(++tgt, tid, cta);   // barrier 2: z complete

        // ============ LayerNorm: CTAs 0..63, one batch row each ==============
        if (cta < 64) {
            int r = cta, u = tid;
            float v = __ldcg(&g_zT[(u >> 1) * 128 + r * 2 + (u & 1)]);
            float s1 = v, s2 = v * v;
            #pragma unroll
            for (int o = 16; o > 0; o >>= 1) {
                s1 += __shfl_xor_sync(0xffffffffu, s1, o);
                s2 += __shfl_xor_sync(0xffffffffu, s2, o);
            }
            if (lane == 0) { red[warp] = s1; red[32 + warp] = s2; }
            __syncthreads();
            float S = 0.f, SS = 0.f;
            #pragma unroll
            for (int w = 0; w < 16; ++w) { S += red[w]; SS += red[32 + w]; }
            float mu   = S * (1.0f / 512.0f);
            float var  = SS * (1.0f / 512.0f) - mu * mu;
            float rstd = rsqrtf(var + 1e-3f);
            float hv = (v - mu) * rstd * __ldg(&gmm[u]) + __ldg(&bta[u]);
            __stcg(&g_hT[(u >> 1) * 128 + r * 2 + (u & 1)], hv);
            y[((size_t)r * 1024 + step) * 512 + u] = hv;
        }
        gbar(++tgt, tid, cta);   // barrier 3: h ready for next step
    }
}

extern "C" void kernel_launch(void* const* d_in, const int* in_sizes, int n_in,
                              void* d_out, int out_size)
{
    const float* x    = (const float*)d_in[0];
    const float* h0   = (const float*)d_in[1];
    const float* Wg   = (const float*)d_in[2];
    const float* bg   = (const float*)d_in[3];
    const float* Wf   = (const float*)d_in[4];
    const float* bf   = (const float*)d_in[5];
    const float* gmm  = (const float*)d_in[6];
    const float* bta  = (const float*)d_in[7];
    float* y = (float*)d_out;

    int smem_bytes = SMEM_FLOATS * (int)sizeof(float);   // 65,792 B
    cudaFuncSetAttribute(fgru_kernel,
                         cudaFuncAttributeMaxDynamicSharedMemorySize, smem_bytes);

    fgru_kernel<<<NCTA, NTHR, smem_bytes>>>(x, h0, Wg, bg, Wf, bf, gmm, bta, y);
}

// round 10
// speedup vs baseline: 1.5188x; 1.5188x over previous
#include <cuda_runtime.h>
#include <cstdint>

// FGRU: B=64, T=1024, D=512, U=512, C=1024
// Persistent kernel: 128 CTAs x 512 threads.
// - direct-L2 GEMMs with 8-deep software-pipelined prefetch (latency hiding)
// - packed f32x2 FMA over K-parity (pair-interleaved layouts)
// - per-warp k-split covers BOTH x-half and h-half of GEMM1; x-partials are
//   computed before the h-ready wait (overlaps previous step's LayerNorm)
// - flag-array barriers; dedicated early h-ready flags from LN CTAs

#define NCTA 128
#define NTHR 512

// pair-interleaved scratch, padded by 8 kp (=1024 floats) for over-prefetch
__device__ __align__(16) float g_xT[1024u * 512u * 64u + 1024u];   // ~128 MB
__device__ __align__(16) float g_hT[512 * 64 + 1024];
__device__ __align__(16) float g_aT[1024 * 64 + 1024];
__device__ __align__(16) float g_zT[512 * 64];
__device__ unsigned g_flag[NCTA];     // full barriers (zero-init)
__device__ unsigned g_hflag[64];      // h-ready flags from LN CTAs

// SMEM layout (floats)
#define OFF_WG2 0                      // [512 kp][8 col][2 par] = 8192
#define OFF_WF2 8192                   // [512 kp][4 col][2 par] = 4096
#define OFF_RED 12288                  // 64x65 tile / reduction = 4160
#define SMEM_FLOATS 16448              // 65,792 bytes

#define FMA2(acc, a, b) \
    asm("fma.rn.f32x2 %0, %1, %2, %0;" : "+l"(acc) : "l"(a), "l"(b))

__device__ __forceinline__ float psum(unsigned long long v)
{
    return __uint_as_float((unsigned)v) + __uint_as_float((unsigned)(v >> 32));
}

// 8-col GEMM segment, 8-deep prefetch. ap stride 64 ull per kp, wp 4 u2 per kp.
template <int NKP>
__device__ __forceinline__ void mm8(const unsigned long long* __restrict__ ap,
                                    const ulonglong2* __restrict__ wp,
                                    unsigned long long* acc)
{
    unsigned long long buf[8];
#pragma unroll
    for (int i = 0; i < 8; ++i) buf[i] = __ldcg(ap + i * 64);
    const unsigned long long* apn = ap + 512;
#pragma unroll
    for (int kb = 0; kb < NKP / 8; ++kb) {
#pragma unroll
        for (int i = 0; i < 8; ++i) {
            unsigned long long av = buf[i];
            buf[i] = __ldcg(apn); apn += 64;        // over-prefetch -> padding
            ulonglong2 w01 = wp[0], w23 = wp[1], w45 = wp[2], w67 = wp[3];
            wp += 4;
            FMA2(acc[0], av, w01.x); FMA2(acc[1], av, w01.y);
            FMA2(acc[2], av, w23.x); FMA2(acc[3], av, w23.y);
            FMA2(acc[4], av, w45.x); FMA2(acc[5], av, w45.y);
            FMA2(acc[6], av, w67.x); FMA2(acc[7], av, w67.y);
        }
    }
}

// 4-col GEMM segment, 8-deep prefetch. wp stride 2 u2 per kp.
template <int NKP>
__device__ __forceinline__ void mm4(const unsigned long long* __restrict__ ap,
                                    const ulonglong2* __restrict__ wp,
                                    unsigned long long* acc)
{
    unsigned long long buf[8];
#pragma unroll
    for (int i = 0; i < 8; ++i) buf[i] = __ldcg(ap + i * 64);
    const unsigned long long* apn = ap + 512;
#pragma unroll
    for (int kb = 0; kb < NKP / 8; ++kb) {
#pragma unroll
        for (int i = 0; i < 8; ++i) {
            unsigned long long av = buf[i];
            buf[i] = __ldcg(apn); apn += 64;
            ulonglong2 w01 = wp[0], w23 = wp[1];
            wp += 2;
            FMA2(acc[0], av, w01.x); FMA2(acc[1], av, w01.y);
            FMA2(acc[2], av, w23.x); FMA2(acc[3], av, w23.y);
        }
    }
}

__global__ void __launch_bounds__(NTHR, 1)
fgru_kernel(const float* __restrict__ x,      // [64][1024][512]
            const float* __restrict__ h0,     // [64][512]
            const float* __restrict__ Wg,     // [1024][1024]
            const float* __restrict__ bg,     // [1024]
            const float* __restrict__ Wf,     // [1024][512]
            const float* __restrict__ bf,     // [512]
            const float* __restrict__ gmm,    // [512]
            const float* __restrict__ bta,    // [512]
            float* __restrict__ y)            // [64][1024][512]
{
    extern __shared__ __align__(16) float sm[];
    float* red = sm + OFF_RED;

    const int tid  = threadIdx.x;
    const int cta  = blockIdx.x;
    const int gc0  = cta * 8;
    const int fc0  = cta * 4;
    const int lane = tid & 31;
    const int warp = tid >> 5;         // 0..15
    const int rowg = warp & 1;
    const int ks   = warp >> 1;        // 0..7
    const int row  = rowg * 32 + lane;

    // ---------- one-time: weights into SMEM, pair-interleaved over k ----------
    for (int e = tid; e < 8192; e += NTHR) {
        int c = e & 7, k = e >> 3;
        sm[OFF_WG2 + (k >> 1) * 16 + c * 2 + (k & 1)] = Wg[k * 1024 + gc0 + c];
    }
    for (int e = tid; e < 4096; e += NTHR) {
        int c = e & 3, k = e >> 2;
        sm[OFF_WF2 + (k >> 1) * 8 + c * 2 + (k & 1)] = Wf[k * 512 + fc0 + c];
    }

    // ---------- one-time: h0 -> g_hT ----------
    {
        int g = cta * NTHR + tid;
        if (g < 32768) {
            int u = g >> 6, r = g & 63;
            __stcg(&g_hT[(u >> 1) * 128 + r * 2 + (u & 1)], h0[r * 512 + u]);
        }
    }

    // ---------- one-time: transpose x -> g_xT (8 t-slices per CTA) ----------
    {
        float* tile = red;             // 64 x 65
        for (int i = 0; i < 8; ++i) {
            int t = cta * 8 + i;
            for (int kc = 0; kc < 8; ++kc) {
                __syncthreads();
                int kloc = tid & 63, rbase = tid >> 6;
                #pragma unroll
                for (int p = 0; p < 8; ++p) {
                    int r = p * 8 + rbase;
                    tile[kloc * 65 + r] =
                        x[((size_t)r * 1024 + t) * 512 + kc * 64 + kloc];
                }
                __syncthreads();
                #pragma unroll
                for (int it = 0; it < 2; ++it) {
                    int f4 = tid + NTHR * it;        // 0..1023
                    int kploc = f4 >> 5, q = f4 & 31;
                    float4 v;
                    v.x = tile[(2 * kploc) * 65 + 2 * q];
                    v.y = tile[(2 * kploc + 1) * 65 + 2 * q];
                    v.z = tile[(2 * kploc) * 65 + 2 * q + 1];
                    v.w = tile[(2 * kploc + 1) * 65 + 2 * q + 1];
                    reinterpret_cast<float4*>(g_xT)
                        [(size_t)t * 8192 + (kc * 32 + kploc) * 32 + q] = v;
                }
            }
        }
    }

    // ---------- barrier bases (uniform at launch start; graph-replay safe) ---
    __shared__ unsigned s_f, s_h;
    if (tid == 0) s_f = *((volatile unsigned*)&g_flag[cta]);
    if (tid == 32) s_h = *((volatile unsigned*)&g_hflag[cta & 63]);
    __syncthreads();
    const unsigned fbase = s_f, hbase = s_h;
    unsigned ftgt = fbase;

    // init barrier (full)
    {
        ++ftgt;
        __syncthreads();
        if (tid == 0) { __threadfence(); *((volatile unsigned*)&g_flag[cta]) = ftgt; }
        if (tid < NCTA) while (*((volatile unsigned*)&g_flag[tid]) < ftgt) { }
        __threadfence();
        __syncthreads();
    }

    const ulonglong2* wg2 = reinterpret_cast<const ulonglong2*>(sm + OFF_WG2);
    const ulonglong2* wf2 = reinterpret_cast<const ulonglong2*>(sm + OFF_WF2);
    const unsigned long long* hT64 =
        reinterpret_cast<const unsigned long long*>(g_hT);
    const unsigned long long* aT64 =
        reinterpret_cast<const unsigned long long*>(g_aT);
    const unsigned long long* xT64 =
        reinterpret_cast<const unsigned long long*>(g_xT);

    const ulonglong2* wpx = wg2 + (ks * 32) * 4;          // x-K rows
    const ulonglong2* wph = wg2 + (256 + ks * 32) * 4;    // h-K rows
    const ulonglong2* wpf = wf2 + (ks * 64) * 2;

    for (int step = 0; step < 1024; ++step) {
        unsigned long long acc[8] = {0, 0, 0, 0, 0, 0, 0, 0};

        // ===== GEMM1 x-partials: no dependency on this step's h ==============
        mm8<32>(xT64 + (size_t)step * 16384 + (ks * 32) * 64 + row, wpx, acc);

        // ===== wait h-ready (prev step's LN), early-signaled flags ===========
        {
            unsigned htgt = hbase + (unsigned)step;
            if (step > 0 && tid < 64) {
                while (*((volatile unsigned*)&g_hflag[tid]) < htgt) { }
            }
            __threadfence();
            __syncthreads();
        }

        // ===== GEMM1 h-partials ==============================================
        mm8<32>(hT64 + (ks * 32) * 64 + row, wph, acc);

        {
            float* rb = red + row;
            #pragma unroll
            for (int c = 0; c < 8; ++c) rb[65 * (c + 8 * ks)] = psum(acc[c]);
        }
        __syncthreads();

        // ===== epilogue 1: gate = sigmoid, a = combined * gate ===============
        {
            int r = tid & 63, c = tid >> 6;       // c in 0..7
            float sum = 0.f;
            #pragma unroll
            for (int ss = 0; ss < 8; ++ss) sum += red[r + 65 * (c + 8 * ss)];
            int gc = gc0 + c;
            float pre  = sum + __ldg(&bg[gc]);
            float gate = 1.0f / (1.0f + __expf(-pre));
            float cv;
            if (gc0 < 512) {
                cv = __ldcg(&g_xT[(size_t)step * 32768 +
                                  (gc >> 1) * 128 + r * 2 + (gc & 1)]);
            } else {
                int u = gc - 512;
                cv = __ldcg(&g_hT[(u >> 1) * 128 + r * 2 + (u & 1)]);
            }
            __stcg(&g_aT[(gc >> 1) * 128 + r * 2 + (gc & 1)], cv * gate);
        }

        // ===== barrier B: a complete (full) ==================================
        {
            ++ftgt;
            __syncthreads();
            if (tid == 0) { __threadfence(); *((volatile unsigned*)&g_flag[cta]) = ftgt; }
            if (tid < NCTA) while (*((volatile unsigned*)&g_flag[tid]) < ftgt) { }
            __threadfence();
            __syncthreads();
        }

        // ===== GEMM2: z_pre = a @ Wf[:, fc0..fc0+4) ==========================
        {
            unsigned long long zac[4] = {0, 0, 0, 0};
            mm4<64>(aT64 + (ks * 64) * 64 + row, wpf, zac);
            float* rb = red + row;
            #pragma unroll
            for (int c = 0; c < 4; ++c) rb[65 * (c + 4 * ks)] = psum(zac[c]);
        }
        __syncthreads();

        // ===== epilogue 2: silu -> g_zT ======================================
        if (tid < 256) {
            int r = tid & 63, c = tid >> 6;       // c in 0..3
            float sum = 0.f;
            #pragma unroll
            for (int ss = 0; ss < 8; ++ss) sum += red[r + 65 * (c + 4 * ss)];
            float z  = sum + __ldg(&bf[fc0 + c]);
            float zs = z / (1.0f + __expf(-z));   // silu
            int gz = fc0 + c;
            __stcg(&g_zT[(gz >> 1) * 128 + r * 2 + (gz & 1)], zs);
        }

        // ===== barrier C: z complete (full) ==================================
        {
            ++ftgt;
            __syncthreads();
            if (tid == 0) { __threadfence(); *((volatile unsigned*)&g_flag[cta]) = ftgt; }
            if (tid < NCTA) while (*((volatile unsigned*)&g_flag[tid]) < ftgt) { }
            __threadfence();
            __syncthreads();
        }

        // ===== LayerNorm: CTAs 0..63, one batch row each; early h signal =====
        if (cta < 64) {
            int r = cta, u = tid;
            float v = __ldcg(&g_zT[(u >> 1) * 128 + r * 2 + (u & 1)]);
            float s1 = v, s2 = v * v;
            #pragma unroll
            for (int o = 16; o > 0; o >>= 1) {
                s1 += __shfl_xor_sync(0xffffffffu, s1, o);
                s2 += __shfl_xor_sync(0xffffffffu, s2, o);
            }
            if (lane == 0) { red[warp] = s1; red[32 + warp] = s2; }
            __syncthreads();
            float S = 0.f, SS = 0.f;
            #pragma unroll
            for (int w = 0; w < 16; ++w) { S += red[w]; SS += red[32 + w]; }
            float mu   = S * (1.0f / 512.0f);
            float var  = SS * (1.0f / 512.0f) - mu * mu;
            float rstd = rsqrtf(var + 1e-3f);
            float hv = (v - mu) * rstd * __ldg(&gmm[u]) + __ldg(&bta[u]);
            __stcg(&g_hT[(u >> 1) * 128 + r * 2 + (u & 1)], hv);
            y[((size_t)r * 1024 + step) * 512 + u] = hv;
            __syncthreads();
            if (tid == 0) {
                __threadfence();
                *((volatile unsigned*)&g_hflag[cta]) = hbase + (unsigned)step + 1u;
            }
        }
        // no trailing full barrier: next iteration's h-wait orders against LN
    }
}

extern "C" void kernel_launch(void* const* d_in, const int* in_sizes, int n_in,
                              void* d_out, int out_size)
{
    const float* x    = (const float*)d_in[0];
    const float* h0   = (const float*)d_in[1];
    const float* Wg   = (const float*)d_in[2];
    const float* bg   = (const float*)d_in[3];
    const float* Wf   = (const float*)d_in[4];
    const float* bf   = (const float*)d_in[5];
    const float* gmm  = (const float*)d_in[6];
    const float* bta  = (const float*)d_in[7];
    float* y = (float*)d_out;

    int smem_bytes = SMEM_FLOATS * (int)sizeof(float);   // 65,792 B
    cudaFuncSetAttribute(fgru_kernel,
                         cudaFuncAttributeMaxDynamicSharedMemorySize, smem_bytes);

    fgru_kernel<<<NCTA, NTHR, smem_bytes>>>(x, h0, Wg, bg, Wf, bf, gmm, bta, y);
}

// round 11
// speedup vs baseline: 1.6143x; 1.0629x over previous
#include <cuda_runtime.h>
#include <cstdint>

// FGRU: B=64, T=1024, D=512, U=512, C=1024
// Persistent kernel: 128 CTAs x 512 threads.
// Round-11 layout: warp = 16-way K-split covering ALL 64 rows (2 rows/thread),
// halving weight-LDS per FMA2 and doubling per-warp load MLP.
// - direct-L2 GEMMs, 4-deep x 2-stream software pipeline (8 outstanding/warp)
// - packed f32x2 FMA over K-parity (pair-interleaved layouts)
// - x-slice partials computed before the h-ready wait (overlaps prev LN)
// - flag-array barriers; dedicated early h-ready flags from LN CTAs

#define NCTA 128
#define NTHR 512
#define PDEPTH 4

// pair-interleaved scratch, padded 2048 floats for pipeline over-prefetch
__device__ __align__(16) float g_xT[1024u * 512u * 64u + 2048u];   // ~128 MB
__device__ __align__(16) float g_hT[512 * 64 + 2048];
__device__ __align__(16) float g_aT[1024 * 64 + 2048];
__device__ __align__(16) float g_zT[512 * 64];
__device__ unsigned g_flag[NCTA];     // full barriers (zero-init)
__device__ unsigned g_hflag[64];      // h-ready flags from LN CTAs

// SMEM layout (floats)
#define OFF_WG2 0                      // [512 kp][8 col][2 par] = 8192
#define OFF_WF2 8192                   // [512 kp][4 col][2 par] = 4096
#define OFF_RED 12288                  // partials [16 slots][64] x 8c = 8192
#define SMEM_FLOATS 20480              // 81,920 bytes

#define FMA2(acc, a, b) \
    asm("fma.rn.f32x2 %0, %1, %2, %0;" : "+l"(acc) : "l"(a), "l"(b))

__device__ __forceinline__ float psum(unsigned long long v)
{
    return __uint_as_float((unsigned)v) + __uint_as_float((unsigned)(v >> 32));
}

// GEMM segment: NKP kp-iterations, NC cols, 2 row-streams (lane, lane+32).
// ap: activation base + lane (stride 64 ull per kp; +32 for second row).
// wp: weights, NC/2 ulonglong2 per kp. acc: [2*NC] (cols for row l, then l+32).
template <int NKP, int NC>
__device__ __forceinline__ void mmseg(const unsigned long long* __restrict__ ap,
                                      const ulonglong2* __restrict__ wp,
                                      unsigned long long* acc)
{
    unsigned long long bufA[PDEPTH], bufB[PDEPTH];
#pragma unroll
    for (int i = 0; i < PDEPTH; ++i) {
        bufA[i] = __ldcg(ap + i * 64);
        bufB[i] = __ldcg(ap + i * 64 + 32);
    }
    const unsigned long long* apn = ap + PDEPTH * 64;
#pragma unroll
    for (int kb = 0; kb < NKP / PDEPTH; ++kb) {
#pragma unroll
        for (int i = 0; i < PDEPTH; ++i) {
            unsigned long long avA = bufA[i], avB = bufB[i];
            bufA[i] = __ldcg(apn);            // over-prefetch -> padding
            bufB[i] = __ldcg(apn + 32);
            apn += 64;
#pragma unroll
            for (int cq = 0; cq < NC / 2; ++cq) {
                ulonglong2 w = wp[cq];
                FMA2(acc[2 * cq + 0],      avA, w.x);
                FMA2(acc[2 * cq + 1],      avA, w.y);
                FMA2(acc[NC + 2 * cq + 0], avB, w.x);
                FMA2(acc[NC + 2 * cq + 1], avB, w.y);
            }
            wp += NC / 2;
        }
    }
}

__global__ void __launch_bounds__(NTHR, 1)
fgru_kernel(const float* __restrict__ x,      // [64][1024][512]
            const float* __restrict__ h0,     // [64][512]
            const float* __restrict__ Wg,     // [1024][1024]
            const float* __restrict__ bg,     // [1024]
            const float* __restrict__ Wf,     // [1024][512]
            const float* __restrict__ bf,     // [512]
            const float* __restrict__ gmm,    // [512]
            const float* __restrict__ bta,    // [512]
            float* __restrict__ y)            // [64][1024][512]
{
    extern __shared__ __align__(16) float sm[];
    float* red = sm + OFF_RED;

    const int tid  = threadIdx.x;
    const int cta  = blockIdx.x;
    const int gc0  = cta * 8;
    const int fc0  = cta * 4;
    const int lane = tid & 31;
    const int warp = tid >> 5;         // 0..15 = K-split group

    // ---------- one-time: weights into SMEM, pair-interleaved over k ----------
    for (int e = tid; e < 8192; e += NTHR) {
        int c = e & 7, k = e >> 3;
        sm[OFF_WG2 + (k >> 1) * 16 + c * 2 + (k & 1)] = Wg[k * 1024 + gc0 + c];
    }
    for (int e = tid; e < 4096; e += NTHR) {
        int c = e & 3, k = e >> 2;
        sm[OFF_WF2 + (k >> 1) * 8 + c * 2 + (k & 1)] = Wf[k * 512 + fc0 + c];
    }

    // ---------- one-time: h0 -> g_hT ----------
    {
        int g = cta * NTHR + tid;
        if (g < 32768) {
            int u = g >> 6, r = g & 63;
            __stcg(&g_hT[(u >> 1) * 128 + r * 2 + (u & 1)], h0[r * 512 + u]);
        }
    }

    // ---------- one-time: transpose x -> g_xT (8 t-slices per CTA) ----------
    {
        float* tile = red;             // 64 x 65 (fits in 8192-float red)
        for (int i = 0; i < 8; ++i) {
            int t = cta * 8 + i;
            for (int kc = 0; kc < 8; ++kc) {
                __syncthreads();
                int kloc = tid & 63, rbase = tid >> 6;
                #pragma unroll
                for (int p = 0; p < 8; ++p) {
                    int r = p * 8 + rbase;
                    tile[kloc * 65 + r] =
                        x[((size_t)r * 1024 + t) * 512 + kc * 64 + kloc];
                }
                __syncthreads();
                #pragma unroll
                for (int it = 0; it < 2; ++it) {
                    int f4 = tid + NTHR * it;        // 0..1023
                    int kploc = f4 >> 5, q = f4 & 31;
                    float4 v;
                    v.x = tile[(2 * kploc) * 65 + 2 * q];
                    v.y = tile[(2 * kploc + 1) * 65 + 2 * q];
                    v.z = tile[(2 * kploc) * 65 + 2 * q + 1];
                    v.w = tile[(2 * kploc + 1) * 65 + 2 * q + 1];
                    reinterpret_cast<float4*>(g_xT)
                        [(size_t)t * 8192 + (kc * 32 + kploc) * 32 + q] = v;
                }
            }
        }
    }

    // ---------- barrier bases (uniform at launch start; graph-replay safe) ---
    __shared__ unsigned s_f, s_h;
    if (tid == 0) s_f = *((volatile unsigned*)&g_flag[cta]);
    if (tid == 32) s_h = *((volatile unsigned*)&g_hflag[cta & 63]);
    __syncthreads();
    const unsigned fbase = s_f, hbase = s_h;
    unsigned ftgt = fbase;

    // init barrier (full)
    {
        ++ftgt;
        __syncthreads();
        if (tid == 0) { __threadfence(); *((volatile unsigned*)&g_flag[cta]) = ftgt; }
        if (tid < NCTA) while (*((volatile unsigned*)&g_flag[tid]) < ftgt) { }
        __threadfence();
        __syncthreads();
    }

    const ulonglong2* wg2 = reinterpret_cast<const ulonglong2*>(sm + OFF_WG2);
    const ulonglong2* wf2 = reinterpret_cast<const ulonglong2*>(sm + OFF_WF2);
    const unsigned long long* hT64 =
        reinterpret_cast<const unsigned long long*>(g_hT);
    const unsigned long long* aT64 =
        reinterpret_cast<const unsigned long long*>(g_aT);
    const unsigned long long* xT64 =
        reinterpret_cast<const unsigned long long*>(g_xT);

    // per-warp K-slices (16-way split)
    const ulonglong2* wpx = wg2 + (warp * 16) * 4;          // x: kp [16w,16w+16)
    const ulonglong2* wph = wg2 + (256 + warp * 16) * 4;    // h: kp 256+[16w,..)
    const ulonglong2* wpf = wf2 + (warp * 32) * 2;          // a: kp [32w,32w+32)

    for (int step = 0; step < 1024; ++step) {
        unsigned long long acc[16];
        #pragma unroll
        for (int i = 0; i < 16; ++i) acc[i] = 0ull;

        // ===== GEMM1 x-partials: independent of this step's h ================
        mmseg<16, 8>(xT64 + (size_t)step * 16384 + (warp * 16) * 64 + lane,
                     wpx, acc);

        // ===== wait h-ready (prev step's LN), early-signaled flags ===========
        {
            unsigned htgt = hbase + (unsigned)step;
            if (step > 0 && tid < 64) {
                while (*((volatile unsigned*)&g_hflag[tid]) < htgt) { }
            }
            __threadfence();
            __syncthreads();
        }

        // ===== GEMM1 h-partials ==============================================
        mmseg<16, 8>(hT64 + (warp * 16) * 64 + lane, wph, acc);

        {
            #pragma unroll
            for (int c = 0; c < 8; ++c) {
                red[(c * 16 + warp) * 64 + lane]      = psum(acc[c]);
                red[(c * 16 + warp) * 64 + lane + 32] = psum(acc[8 + c]);
            }
        }
        __syncthreads();

        // ===== epilogue 1: gate = sigmoid, a = combined * gate ===============
        {
            int r = tid & 63, c = tid >> 6;       // c in 0..7
            float sum = 0.f;
            #pragma unroll
            for (int w = 0; w < 16; ++w) sum += red[(c * 16 + w) * 64 + r];
            int gc = gc0 + c;
            float pre  = sum + __ldg(&bg[gc]);
            float gate = 1.0f / (1.0f + __expf(-pre));
            float cv;
            if (gc0 < 512) {
                cv = __ldcg(&g_xT[(size_t)step * 32768 +
                                  (gc >> 1) * 128 + r * 2 + (gc & 1)]);
            } else {
                int u = gc - 512;
                cv = __ldcg(&g_hT[(u >> 1) * 128 + r * 2 + (u & 1)]);
            }
            __stcg(&g_aT[(gc >> 1) * 128 + r * 2 + (gc & 1)], cv * gate);
        }

        // ===== barrier B: a complete (full) ==================================
        {
            ++ftgt;
            __syncthreads();
            if (tid == 0) { __threadfence(); *((volatile unsigned*)&g_flag[cta]) = ftgt; }
            if (tid < NCTA) while (*((volatile unsigned*)&g_flag[tid]) < ftgt) { }
            __threadfence();
            __syncthreads();
        }

        // ===== GEMM2: z_pre = a @ Wf[:, fc0..fc0+4) ==========================
        {
            unsigned long long zac[8];
            #pragma unroll
            for (int i = 0; i < 8; ++i) zac[i] = 0ull;
            mmseg<32, 4>(aT64 + (warp * 32) * 64 + lane, wpf, zac);
            #pragma unroll
            for (int c = 0; c < 4; ++c) {
                red[(c * 16 + warp) * 64 + lane]      = psum(zac[c]);
                red[(c * 16 + warp) * 64 + lane + 32] = psum(zac[4 + c]);
            }
        }
        __syncthreads();

        // ===== epilogue 2: silu -> g_zT ======================================
        if (tid < 256) {
            int r = tid & 63, c = tid >> 6;       // c in 0..3
            float sum = 0.f;
            #pragma unroll
            for (int w = 0; w < 16; ++w) sum += red[(c * 16 + w) * 64 + r];
            float z  = sum + __ldg(&bf[fc0 + c]);
            float zs = z / (1.0f + __expf(-z));   // silu
            int gz = fc0 + c;
            __stcg(&g_zT[(gz >> 1) * 128 + r * 2 + (gz & 1)], zs);
        }

        // ===== barrier C: z complete (full) ==================================
        {
            ++ftgt;
            __syncthreads();
            if (tid == 0) { __threadfence(); *((volatile unsigned*)&g_flag[cta]) = ftgt; }
            if (tid < NCTA) while (*((volatile unsigned*)&g_flag[tid]) < ftgt) { }
            __threadfence();
            __syncthreads();
        }

        // ===== LayerNorm: CTAs 0..63, one batch row each; early h signal =====
        if (cta < 64) {
            int r = cta, u = tid;
            float v = __ldcg(&g_zT[(u >> 1) * 128 + r * 2 + (u & 1)]);
            float s1 = v, s2 = v * v;
            #pragma unroll
            for (int o = 16; o > 0; o >>= 1) {
                s1 += __shfl_xor_sync(0xffffffffu, s1, o);
                s2 += __shfl_xor_sync(0xffffffffu, s2, o);
            }
            if (lane == 0) { red[warp] = s1; red[32 + warp] = s2; }
            __syncthreads();
            float S = 0.f, SS = 0.f;
            #pragma unroll
            for (int w = 0; w < 16; ++w) { S += red[w]; SS += red[32 + w]; }
            float mu   = S * (1.0f / 512.0f);
            float var  = SS * (1.0f / 512.0f) - mu * mu;
            float rstd = rsqrtf(var + 1e-3f);
            float hv = (v - mu) * rstd * __ldg(&gmm[u]) + __ldg(&bta[u]);
            __stcg(&g_hT[(u >> 1) * 128 + r * 2 + (u & 1)], hv);
            y[((size_t)r * 1024 + step) * 512 + u] = hv;
            __syncthreads();
            if (tid == 0) {
                __threadfence();
                *((volatile unsigned*)&g_hflag[cta]) = hbase + (unsigned)step + 1u;
            }
        }
        // no trailing full barrier: next iteration's h-wait orders against LN
    }
}

extern "C" void kernel_launch(void* const* d_in, const int* in_sizes, int n_in,
                              void* d_out, int out_size)
{
    const float* x    = (const float*)d_in[0];
    const float* h0   = (const float*)d_in[1];
    const float* Wg   = (const float*)d_in[2];
    const float* bg   = (const float*)d_in[3];
    const float* Wf   = (const float*)d_in[4];
    const float* bf   = (const float*)d_in[5];
    const float* gmm  = (const float*)d_in[6];
    const float* bta  = (const float*)d_in[7];
    float* y = (float*)d_out;

    int smem_bytes = SMEM_FLOATS * (int)sizeof(float);   // 81,920 B
    cudaFuncSetAttribute(fgru_kernel,
                         cudaFuncAttributeMaxDynamicSharedMemorySize, smem_bytes);

    fgru_kernel<<<NCTA, NTHR, smem_bytes>>>(x, h0, Wg, bg, Wf, bf, gmm, bta, y);
}